// round 1
// baseline (speedup 1.0000x reference)
#include <cuda_runtime.h>
#include <cuda_bf16.h>
#include <cstdint>
#include <cstddef>

// Problem constants
#define S_LEN 16384
#define D_HID 1280
#define H_NUM 16
#define HD_DIM 80
#define WS_WIN 64
#define NW_WIN (S_LEN / WS_WIN)   // 256
#define QKV_N (3 * D_HID)         // 3840

// Scratch (device globals: allocation-free contract)
__device__ float g_qkv[(size_t)S_LEN * QKV_N];   // 16384 x 3840  (q|k|v row-major)
__device__ float g_attn[(size_t)S_LEN * D_HID];  // 16384 x 1280  (attention output)

// ---------------------------------------------------------------------------
// NT GEMM: C[M,N] = A[M,K] * B[N,K]^T + bias[N]
// A row-major (K contiguous), B row-major (K contiguous) -> both K-major.
// Tile 128x128, BK=8, 256 threads, 8x8 per thread (4+4 split), double buffered.
// M, N multiples of 128; K multiple of 8. No bounds checks needed.
// ---------------------------------------------------------------------------
#define BM 128
#define BN 128
#define BK 8
#define SMEM_LD 132   // padded row stride (floats) to dodge store conflicts

__global__ __launch_bounds__(256, 2) void gemm_nt_bias(
    const float* __restrict__ A, const float* __restrict__ B,
    const float* __restrict__ bias, float* __restrict__ C,
    int K, int N)
{
    __shared__ float As[2][BK][SMEM_LD];
    __shared__ float Bs[2][BK][SMEM_LD];

    const int tid = threadIdx.x;
    const int m0 = blockIdx.y * BM;
    const int n0 = blockIdx.x * BN;
    const int tx = tid & 15;       // 0..15 -> N
    const int ty = tid >> 4;       // 0..15 -> M

    // tile-load mapping: 128 rows x 8 k, float4 per thread
    const int lrow = tid >> 1;            // 0..127
    const int lk   = (tid & 1) * 4;       // 0 or 4

    const float* Aptr = A + (size_t)(m0 + lrow) * K + lk;
    const float* Bptr = B + (size_t)(n0 + lrow) * K + lk;

    float acc[8][8];
    #pragma unroll
    for (int i = 0; i < 8; i++)
        #pragma unroll
        for (int j = 0; j < 8; j++)
            acc[i][j] = 0.f;

    // prefetch tile 0
    float4 ra = *(const float4*)Aptr;
    float4 rb = *(const float4*)Bptr;
    As[0][lk + 0][lrow] = ra.x; As[0][lk + 1][lrow] = ra.y;
    As[0][lk + 2][lrow] = ra.z; As[0][lk + 3][lrow] = ra.w;
    Bs[0][lk + 0][lrow] = rb.x; Bs[0][lk + 1][lrow] = rb.y;
    Bs[0][lk + 2][lrow] = rb.z; Bs[0][lk + 3][lrow] = rb.w;
    __syncthreads();

    const int ktiles = K / BK;
    int buf = 0;

    for (int kt = 0; kt < ktiles; kt++) {
        if (kt + 1 < ktiles) {
            ra = *(const float4*)(Aptr + (kt + 1) * BK);
            rb = *(const float4*)(Bptr + (kt + 1) * BK);
        }

        #pragma unroll
        for (int kk = 0; kk < BK; kk++) {
            float a[8], b[8];
            float4 t;
            t = *(const float4*)&As[buf][kk][ty * 4];
            a[0] = t.x; a[1] = t.y; a[2] = t.z; a[3] = t.w;
            t = *(const float4*)&As[buf][kk][64 + ty * 4];
            a[4] = t.x; a[5] = t.y; a[6] = t.z; a[7] = t.w;
            t = *(const float4*)&Bs[buf][kk][tx * 4];
            b[0] = t.x; b[1] = t.y; b[2] = t.z; b[3] = t.w;
            t = *(const float4*)&Bs[buf][kk][64 + tx * 4];
            b[4] = t.x; b[5] = t.y; b[6] = t.z; b[7] = t.w;

            #pragma unroll
            for (int i = 0; i < 8; i++)
                #pragma unroll
                for (int j = 0; j < 8; j++)
                    acc[i][j] = fmaf(a[i], b[j], acc[i][j]);
        }

        if (kt + 1 < ktiles) {
            buf ^= 1;
            As[buf][lk + 0][lrow] = ra.x; As[buf][lk + 1][lrow] = ra.y;
            As[buf][lk + 2][lrow] = ra.z; As[buf][lk + 3][lrow] = ra.w;
            Bs[buf][lk + 0][lrow] = rb.x; Bs[buf][lk + 1][lrow] = rb.y;
            Bs[buf][lk + 2][lrow] = rb.z; Bs[buf][lk + 3][lrow] = rb.w;
            __syncthreads();
        }
    }

    // epilogue: bias + store
    float b0[4], b1[4];
    #pragma unroll
    for (int j = 0; j < 4; j++) {
        b0[j] = bias[n0 + tx * 4 + j];
        b1[j] = bias[n0 + 64 + tx * 4 + j];
    }
    #pragma unroll
    for (int i = 0; i < 8; i++) {
        int row = m0 + ((i < 4) ? (ty * 4 + i) : (64 + ty * 4 + i - 4));
        float4 v0, v1;
        v0.x = acc[i][0] + b0[0]; v0.y = acc[i][1] + b0[1];
        v0.z = acc[i][2] + b0[2]; v0.w = acc[i][3] + b0[3];
        v1.x = acc[i][4] + b1[0]; v1.y = acc[i][5] + b1[1];
        v1.z = acc[i][6] + b1[2]; v1.w = acc[i][7] + b1[3];
        *(float4*)&C[(size_t)row * N + n0 + tx * 4] = v0;
        *(float4*)&C[(size_t)row * N + n0 + 64 + tx * 4] = v1;
    }
}

// ---------------------------------------------------------------------------
// Windowed attention, one block per (window, head).
// Loads q/k/v (64x80) from the QKV buffer, applies RoPE on the fly,
// computes softmax(q k^T * scale + mask) v, writes [S, H*HD] layout.
// ---------------------------------------------------------------------------
#define Q_LD 81   // padded (81 mod 32 = 17, coprime -> conflict-free column reads)
#define P_LD 65

__global__ __launch_bounds__(256) void attn_kernel(
    const float* __restrict__ qkv,
    const float* __restrict__ mask,
    const float* __restrict__ cosv,
    const float* __restrict__ sinv,
    float* __restrict__ out)
{
    extern __shared__ float sm[];
    float* qs = sm;                       // 64 * 81
    float* ks = qs + 64 * Q_LD;
    float* vs = ks + 64 * Q_LD;
    float* ps = vs + 64 * Q_LD;           // 64 * 65

    const int w = blockIdx.x >> 4;        // window
    const int h = blockIdx.x & 15;        // head
    const int tid = threadIdx.x;

    // load + RoPE
    for (int idx = tid; idx < WS_WIN * HD_DIM; idx += 256) {
        const int p = idx / HD_DIM, d = idx % HD_DIM;
        const int s = w * WS_WIN + p;
        const size_t base = (size_t)s * QKV_N + h * HD_DIM;
        const float c  = cosv[s * HD_DIM + d];
        const float sn = sinv[s * HD_DIM + d];
        const int pd   = (d < 40) ? (d + 40) : (d - 40);
        const float sg = (d < 40) ? -1.f : 1.f;

        float qv = qkv[base + d];
        float qp = qkv[base + pd];
        qs[p * Q_LD + d] = qv * c + sg * qp * sn;

        float kv = qkv[base + D_HID + d];
        float kp = qkv[base + D_HID + pd];
        ks[p * Q_LD + d] = kv * c + sg * kp * sn;

        vs[p * Q_LD + d] = qkv[base + 2 * D_HID + d];
    }
    __syncthreads();

    // scores + softmax: warp per 8 rows, lane holds cols {lane, lane+32}
    const float scale = 0.1118033988749895f;  // 1/sqrt(80)
    const int warp = tid >> 5, lane = tid & 31;
    const float* mrow_base = mask + (size_t)w * (WS_WIN * WS_WIN);

    #pragma unroll
    for (int i = 0; i < 8; i++) {
        const int r = warp * 8 + i;
        float v0 = 0.f, v1 = 0.f;
        const float* qrow = &qs[r * Q_LD];
        const float* k0 = &ks[lane * Q_LD];
        const float* k1 = &ks[(lane + 32) * Q_LD];
        #pragma unroll 8
        for (int d = 0; d < HD_DIM; d++) {
            const float qd = qrow[d];
            v0 = fmaf(qd, k0[d], v0);
            v1 = fmaf(qd, k1[d], v1);
        }
        v0 = v0 * scale + mrow_base[r * WS_WIN + lane];
        v1 = v1 * scale + mrow_base[r * WS_WIN + lane + 32];

        float mx = fmaxf(v0, v1);
        #pragma unroll
        for (int o = 16; o > 0; o >>= 1)
            mx = fmaxf(mx, __shfl_xor_sync(0xffffffffu, mx, o));
        const float e0 = __expf(v0 - mx);
        const float e1 = __expf(v1 - mx);
        float ssum = e0 + e1;
        #pragma unroll
        for (int o = 16; o > 0; o >>= 1)
            ssum += __shfl_xor_sync(0xffffffffu, ssum, o);
        const float inv = 1.f / ssum;
        ps[r * P_LD + lane]      = e0 * inv;
        ps[r * P_LD + lane + 32] = e1 * inv;
    }
    __syncthreads();

    // O = P * V
    for (int idx = tid; idx < WS_WIN * HD_DIM; idx += 256) {
        const int r = idx / HD_DIM, d = idx % HD_DIM;
        const float* prow = &ps[r * P_LD];
        float acc = 0.f;
        #pragma unroll 8
        for (int c = 0; c < WS_WIN; c++)
            acc = fmaf(prow[c], vs[c * Q_LD + d], acc);
        out[(size_t)(w * WS_WIN + r) * D_HID + h * HD_DIM + d] = acc;
    }
}

// ---------------------------------------------------------------------------
// launch
// ---------------------------------------------------------------------------
extern "C" void kernel_launch(void* const* d_in, const int* in_sizes, int n_in,
                              void* d_out, int out_size)
{
    (void)in_sizes; (void)n_in; (void)out_size;
    const float* hidden = (const float*)d_in[0];
    const float* masks  = (const float*)d_in[1];
    const float* cosv   = (const float*)d_in[2];
    const float* sinv   = (const float*)d_in[3];
    const float* qkv_w  = (const float*)d_in[4];
    const float* qkv_b  = (const float*)d_in[5];
    const float* proj_w = (const float*)d_in[6];
    const float* proj_b = (const float*)d_in[7];
    float* out = (float*)d_out;

    float* qkv_buf;
    float* attn_buf;
    cudaGetSymbolAddress((void**)&qkv_buf, g_qkv);
    cudaGetSymbolAddress((void**)&attn_buf, g_attn);

    // 1) QKV projection: [S, D] @ [3D, D]^T + b -> [S, 3D]
    {
        dim3 grid(QKV_N / BN, S_LEN / BM);
        gemm_nt_bias<<<grid, 256>>>(hidden, qkv_w, qkv_b, qkv_buf, D_HID, QKV_N);
    }

    // 2) windowed attention with fused RoPE
    {
        const int smem = (3 * WS_WIN * Q_LD + WS_WIN * P_LD) * (int)sizeof(float);
        cudaFuncSetAttribute(attn_kernel, cudaFuncAttributeMaxDynamicSharedMemorySize, smem);
        attn_kernel<<<NW_WIN * H_NUM, 256, smem>>>(qkv_buf, masks, cosv, sinv, attn_buf);
    }

    // 3) output projection: [S, D] @ [D, D]^T + b -> [S, D]
    {
        dim3 grid(D_HID / BN, S_LEN / BM);
        gemm_nt_bias<<<grid, 256>>>(attn_buf, proj_w, proj_b, out, D_HID, D_HID);
    }
}

// round 3
// speedup vs baseline: 1.6558x; 1.6558x over previous
#include <cuda_runtime.h>
#include <cuda_bf16.h>
#include <cstdint>
#include <cstddef>

// ---------------------------------------------------------------------------
// Problem constants
// ---------------------------------------------------------------------------
#define S_LEN 16384
#define D_HID 1280
#define H_NUM 16
#define HD_DIM 80
#define WS_WIN 64
#define NW_WIN (S_LEN / WS_WIN)   // 256
#define QKV_N (3 * D_HID)         // 3840
#define KDIM 1280

// GEMM tiling
#define BM 128
#define BN 128
#define BK 32
#define STAGES 3
#define KT_ITERS (KDIM / BK)      // 40
#define STAGE_BYTES 32768         // 4 matrices x 128x32 bf16 (8KB each)
#define GEMM_SMEM (STAGES * STAGE_BYTES)   // 98304

// ---------------------------------------------------------------------------
// Scratch (device globals: allocation-free contract)
// ---------------------------------------------------------------------------
__device__ float g_qkv[(size_t)S_LEN * QKV_N];
__device__ __nv_bfloat16 g_hid_hi[(size_t)S_LEN * D_HID];
__device__ __nv_bfloat16 g_hid_lo[(size_t)S_LEN * D_HID];
__device__ __nv_bfloat16 g_wqkv_hi[(size_t)QKV_N * D_HID];
__device__ __nv_bfloat16 g_wqkv_lo[(size_t)QKV_N * D_HID];
__device__ __nv_bfloat16 g_wproj_hi[(size_t)D_HID * D_HID];
__device__ __nv_bfloat16 g_wproj_lo[(size_t)D_HID * D_HID];
__device__ __nv_bfloat16 g_attn_hi[(size_t)S_LEN * D_HID];
__device__ __nv_bfloat16 g_attn_lo[(size_t)S_LEN * D_HID];

// ---------------------------------------------------------------------------
// PTX helpers (baseline sm_80+ instructions only -- target is plain sm_100)
// ---------------------------------------------------------------------------
__device__ __forceinline__ uint32_t smem_u32(const void* p) {
    uint32_t a;
    asm("{ .reg .u64 t; cvta.to.shared.u64 t, %1; cvt.u32.u64 %0, t; }"
        : "=r"(a) : "l"(p));
    return a;
}

#define CP_ASYNC16(smem_addr, gptr) \
    asm volatile("cp.async.cg.shared.global [%0], [%1], 16;\n" \
                 :: "r"(smem_addr), "l"(gptr))
#define CP_ASYNC_COMMIT() asm volatile("cp.async.commit_group;\n" ::: "memory")
#define CP_ASYNC_WAIT1()  asm volatile("cp.async.wait_group 1;\n" ::: "memory")

#define LDSM_X4(r0, r1, r2, r3, addr) \
    asm volatile("ldmatrix.sync.aligned.m8n8.x4.shared.b16 {%0,%1,%2,%3}, [%4];" \
                 : "=r"(r0), "=r"(r1), "=r"(r2), "=r"(r3) : "r"(addr))

#define MMA16816(d, a0, a1, a2, a3, b0, b1) \
    asm volatile("mma.sync.aligned.m16n8k16.row.col.f32.bf16.bf16.f32 " \
                 "{%0,%1,%2,%3}, {%4,%5,%6,%7}, {%8,%9}, {%0,%1,%2,%3};" \
                 : "+f"((d)[0]), "+f"((d)[1]), "+f"((d)[2]), "+f"((d)[3]) \
                 : "r"(a0), "r"(a1), "r"(a2), "r"(a3), "r"(b0), "r"(b1))

// ---------------------------------------------------------------------------
// bf16x3 mma.sync GEMM: C[M, Ntot] = A[M,1280] * B[Ntot,1280]^T + bias
// A,B supplied as (hi, lo) bf16 K-major pairs. CTA 128x128, BK=32, 3 stages.
// Warp grid 2(M) x 4(N): warp tile 64x32.
// smem per stage: Ah[128][32] Al Bh Bl, xor-swizzled 16B chunks.
// ---------------------------------------------------------------------------
__global__ void __launch_bounds__(256, 1) gemm_bf16x3(
    const __nv_bfloat16* __restrict__ Ah, const __nv_bfloat16* __restrict__ Al,
    const __nv_bfloat16* __restrict__ Bh, const __nv_bfloat16* __restrict__ Bl,
    const float* __restrict__ bias, float* __restrict__ C, int Ntot)
{
    extern __shared__ char smem[];
    const uint32_t sb = smem_u32(smem);
    const int tid = threadIdx.x;
    const int wid = tid >> 5, lane = tid & 31;
    const int warp_m = wid & 1;        // 0..1  (64-row slabs)
    const int warp_n = wid >> 1;       // 0..3  (32-col slabs)
    const int m0 = blockIdx.y * BM;
    const int n0 = blockIdx.x * BN;

    // ---- per-thread cp.async source/dest (8 chunks of 16B per stage) ----
    const __nv_bfloat16* gptr[8];
    uint32_t soff[8];
    #pragma unroll
    for (int t = 0; t < 8; t++) {
        const int idx = tid + t * 256;         // 0..2047
        const int mat = idx >> 9;              // 0:Ah 1:Al 2:Bh 3:Bl
        const int li  = idx & 511;
        const int row = li >> 2;               // 0..127
        const int c   = li & 3;                // 16B chunk within 64B row
        const __nv_bfloat16* base =
            (mat == 0) ? Ah : (mat == 1) ? Al : (mat == 2) ? Bh : Bl;
        const int r0 = ((mat < 2) ? m0 : n0) + row;
        gptr[t] = base + (size_t)r0 * KDIM + c * 8;
        soff[t] = (uint32_t)(mat * 8192 + row * 64 + ((c ^ ((row >> 1) & 3)) << 4));
    }

    // ---- prefetch first STAGES-1 stages ----
    #pragma unroll
    for (int s = 0; s < STAGES - 1; s++) {
        const int kb = s * BK;
        #pragma unroll
        for (int t = 0; t < 8; t++)
            CP_ASYNC16(sb + s * STAGE_BYTES + soff[t], gptr[t] + kb);
        CP_ASYNC_COMMIT();
    }

    // ---- ldmatrix address precompute ----
    // A: lanes 0-15 -> rows (lane&15), lanes 16-31 -> same rows, 2nd 16B chunk
    const int a_row_in = lane & 15;
    const int csel = lane >> 4;                // 0 or 1
    uint32_t aRowOff[4], aXr[4];
    #pragma unroll
    for (int fm = 0; fm < 4; fm++) {
        const int r = warp_m * 64 + fm * 16 + a_row_in;
        aRowOff[fm] = (uint32_t)(r * 64);
        aXr[fm] = (uint32_t)((r >> 1) & 3);
    }
    // B: lanes 0-15 -> n rows (lane&15), x4 loads n16k16 (2 n8 frags)
    uint32_t bRowOff[2], bXr[2];
    #pragma unroll
    for (int bt = 0; bt < 2; bt++) {
        const int r = warp_n * 32 + bt * 16 + a_row_in;
        bRowOff[bt] = (uint32_t)(16384 + r * 64);  // Bh base; +8192 for Bl
        bXr[bt] = (uint32_t)((r >> 1) & 3);
    }

    float acc[4][4][4];
    #pragma unroll
    for (int i = 0; i < 4; i++)
        #pragma unroll
        for (int j = 0; j < 4; j++)
            #pragma unroll
            for (int k = 0; k < 4; k++) acc[i][j][k] = 0.f;

    // ---- main loop ----
    for (int kt = 0; kt < KT_ITERS; kt++) {
        CP_ASYNC_WAIT1();
        __syncthreads();

        // prefetch stage kt+STAGES-1 (overwrites buffer of kt-1, safe post-sync)
        if (kt + STAGES - 1 < KT_ITERS) {
            const int s = (kt + STAGES - 1) % STAGES;
            const int kb = (kt + STAGES - 1) * BK;
            #pragma unroll
            for (int t = 0; t < 8; t++)
                CP_ASYNC16(sb + s * STAGE_BYTES + soff[t], gptr[t] + kb);
        }
        CP_ASYNC_COMMIT();

        const uint32_t stg = sb + (kt % STAGES) * STAGE_BYTES;

        #pragma unroll
        for (int kk = 0; kk < 2; kk++) {
            const uint32_t chunk = (uint32_t)(kk * 2 + csel);

            uint32_t ah[4][4], al[4][4];
            #pragma unroll
            for (int fm = 0; fm < 4; fm++) {
                const uint32_t xoff = ((chunk ^ aXr[fm]) << 4);
                LDSM_X4(ah[fm][0], ah[fm][1], ah[fm][2], ah[fm][3],
                        stg + aRowOff[fm] + xoff);
                LDSM_X4(al[fm][0], al[fm][1], al[fm][2], al[fm][3],
                        stg + 8192 + aRowOff[fm] + xoff);
            }
            uint32_t bh[4][2], bl[4][2];   // [n8 frag][b0,b1]
            #pragma unroll
            for (int bt = 0; bt < 2; bt++) {
                const uint32_t xoff = ((chunk ^ bXr[bt]) << 4);
                uint32_t r0, r1, r2, r3;
                LDSM_X4(r0, r1, r2, r3, stg + bRowOff[bt] + xoff);
                bh[bt * 2 + 0][0] = r0; bh[bt * 2 + 1][0] = r1;
                bh[bt * 2 + 0][1] = r2; bh[bt * 2 + 1][1] = r3;
                LDSM_X4(r0, r1, r2, r3, stg + 8192 + bRowOff[bt] + xoff);
                bl[bt * 2 + 0][0] = r0; bl[bt * 2 + 1][0] = r1;
                bl[bt * 2 + 0][1] = r2; bl[bt * 2 + 1][1] = r3;
            }

            #pragma unroll
            for (int fm = 0; fm < 4; fm++) {
                #pragma unroll
                for (int fn = 0; fn < 4; fn++) {
                    MMA16816(acc[fm][fn], ah[fm][0], ah[fm][1], ah[fm][2], ah[fm][3],
                             bh[fn][0], bh[fn][1]);
                    MMA16816(acc[fm][fn], ah[fm][0], ah[fm][1], ah[fm][2], ah[fm][3],
                             bl[fn][0], bl[fn][1]);
                    MMA16816(acc[fm][fn], al[fm][0], al[fm][1], al[fm][2], al[fm][3],
                             bh[fn][0], bh[fn][1]);
                }
            }
        }
    }

    // ---- epilogue: bias + direct coalesced STG.64 ----
    const int tr = lane >> 2;
    const int tc = (lane & 3) * 2;
    const int r_base = m0 + warp_m * 64;
    const int c_base = n0 + warp_n * 32;
    #pragma unroll
    for (int fn = 0; fn < 4; fn++) {
        const int col = c_base + fn * 8 + tc;
        const float2 bb = *(const float2*)&bias[col];
        #pragma unroll
        for (int fm = 0; fm < 4; fm++) {
            const int row0 = r_base + fm * 16 + tr;
            float2 v0, v1;
            v0.x = acc[fm][fn][0] + bb.x; v0.y = acc[fm][fn][1] + bb.y;
            v1.x = acc[fm][fn][2] + bb.x; v1.y = acc[fm][fn][3] + bb.y;
            *(float2*)&C[(size_t)row0 * Ntot + col] = v0;
            *(float2*)&C[(size_t)(row0 + 8) * Ntot + col] = v1;
        }
    }
}

// ---------------------------------------------------------------------------
// fp32 -> bf16 (hi, lo) split
// ---------------------------------------------------------------------------
__global__ void split_bf16(const float* __restrict__ src,
                           __nv_bfloat16* __restrict__ hi,
                           __nv_bfloat16* __restrict__ lo, int n)
{
    int i = blockIdx.x * blockDim.x + threadIdx.x;
    if (i < n) {
        float x = src[i];
        __nv_bfloat16 h = __float2bfloat16(x);
        hi[i] = h;
        lo[i] = __float2bfloat16(x - __bfloat162float(h));
    }
}

// ---------------------------------------------------------------------------
// Windowed attention (fp32), one block per (window, head).
// ---------------------------------------------------------------------------
#define Q_LD 81
#define P_LD 65

__global__ void __launch_bounds__(256) attn_kernel(
    const float* __restrict__ qkv,
    const float* __restrict__ mask,
    const float* __restrict__ cosv,
    const float* __restrict__ sinv,
    __nv_bfloat16* __restrict__ out_hi,
    __nv_bfloat16* __restrict__ out_lo)
{
    extern __shared__ float sm[];
    float* qs = sm;
    float* ks = qs + 64 * Q_LD;
    float* vs = ks + 64 * Q_LD;
    float* ps = vs + 64 * Q_LD;

    const int w = blockIdx.x >> 4;
    const int h = blockIdx.x & 15;
    const int tid = threadIdx.x;

    for (int idx = tid; idx < WS_WIN * HD_DIM; idx += 256) {
        const int p = idx / HD_DIM, d = idx % HD_DIM;
        const int s = w * WS_WIN + p;
        const size_t base = (size_t)s * QKV_N + h * HD_DIM;
        const float c  = cosv[s * HD_DIM + d];
        const float sn = sinv[s * HD_DIM + d];
        const int pd   = (d < 40) ? (d + 40) : (d - 40);
        const float sg = (d < 40) ? -1.f : 1.f;

        float qv = qkv[base + d];
        float qp = qkv[base + pd];
        qs[p * Q_LD + d] = qv * c + sg * qp * sn;

        float kv = qkv[base + D_HID + d];
        float kp = qkv[base + D_HID + pd];
        ks[p * Q_LD + d] = kv * c + sg * kp * sn;

        vs[p * Q_LD + d] = qkv[base + 2 * D_HID + d];
    }
    __syncthreads();

    const float scale = 0.1118033988749895f;
    const int warp = tid >> 5, lane = tid & 31;
    const float* mrow_base = mask + (size_t)w * (WS_WIN * WS_WIN);

    #pragma unroll
    for (int i = 0; i < 8; i++) {
        const int r = warp * 8 + i;
        float v0 = 0.f, v1 = 0.f;
        const float* qrow = &qs[r * Q_LD];
        const float* k0 = &ks[lane * Q_LD];
        const float* k1 = &ks[(lane + 32) * Q_LD];
        #pragma unroll 8
        for (int d = 0; d < HD_DIM; d++) {
            const float qd = qrow[d];
            v0 = fmaf(qd, k0[d], v0);
            v1 = fmaf(qd, k1[d], v1);
        }
        v0 = v0 * scale + mrow_base[r * WS_WIN + lane];
        v1 = v1 * scale + mrow_base[r * WS_WIN + lane + 32];

        float mx = fmaxf(v0, v1);
        #pragma unroll
        for (int o = 16; o > 0; o >>= 1)
            mx = fmaxf(mx, __shfl_xor_sync(0xffffffffu, mx, o));
        const float e0 = __expf(v0 - mx);
        const float e1 = __expf(v1 - mx);
        float ssum = e0 + e1;
        #pragma unroll
        for (int o = 16; o > 0; o >>= 1)
            ssum += __shfl_xor_sync(0xffffffffu, ssum, o);
        const float inv = 1.f / ssum;
        ps[r * P_LD + lane]      = e0 * inv;
        ps[r * P_LD + lane + 32] = e1 * inv;
    }
    __syncthreads();

    for (int idx = tid; idx < WS_WIN * HD_DIM; idx += 256) {
        const int r = idx / HD_DIM, d = idx % HD_DIM;
        const float* prow = &ps[r * P_LD];
        float acc = 0.f;
        #pragma unroll 8
        for (int c = 0; c < WS_WIN; c++)
            acc = fmaf(prow[c], vs[c * Q_LD + d], acc);
        const size_t o = (size_t)(w * WS_WIN + r) * D_HID + h * HD_DIM + d;
        __nv_bfloat16 hh = __float2bfloat16(acc);
        out_hi[o] = hh;
        out_lo[o] = __float2bfloat16(acc - __bfloat162float(hh));
    }
}

// ---------------------------------------------------------------------------
// launch
// ---------------------------------------------------------------------------
extern "C" void kernel_launch(void* const* d_in, const int* in_sizes, int n_in,
                              void* d_out, int out_size)
{
    (void)in_sizes; (void)n_in; (void)out_size;
    const float* hidden = (const float*)d_in[0];
    const float* masks  = (const float*)d_in[1];
    const float* cosv   = (const float*)d_in[2];
    const float* sinv   = (const float*)d_in[3];
    const float* qkv_w  = (const float*)d_in[4];
    const float* qkv_b  = (const float*)d_in[5];
    const float* proj_w = (const float*)d_in[6];
    const float* proj_b = (const float*)d_in[7];
    float* out = (float*)d_out;

    float* qkv_buf;
    __nv_bfloat16 *hid_hi, *hid_lo, *wqkv_hi, *wqkv_lo, *wproj_hi, *wproj_lo, *attn_hi, *attn_lo;
    cudaGetSymbolAddress((void**)&qkv_buf, g_qkv);
    cudaGetSymbolAddress((void**)&hid_hi, g_hid_hi);
    cudaGetSymbolAddress((void**)&hid_lo, g_hid_lo);
    cudaGetSymbolAddress((void**)&wqkv_hi, g_wqkv_hi);
    cudaGetSymbolAddress((void**)&wqkv_lo, g_wqkv_lo);
    cudaGetSymbolAddress((void**)&wproj_hi, g_wproj_hi);
    cudaGetSymbolAddress((void**)&wproj_lo, g_wproj_lo);
    cudaGetSymbolAddress((void**)&attn_hi, g_attn_hi);
    cudaGetSymbolAddress((void**)&attn_lo, g_attn_lo);

    // 0) fp32 -> bf16 hi/lo splits
    {
        int n1 = S_LEN * D_HID;
        split_bf16<<<(n1 + 255) / 256, 256>>>(hidden, hid_hi, hid_lo, n1);
        int n2 = QKV_N * D_HID;
        split_bf16<<<(n2 + 255) / 256, 256>>>(qkv_w, wqkv_hi, wqkv_lo, n2);
        int n3 = D_HID * D_HID;
        split_bf16<<<(n3 + 255) / 256, 256>>>(proj_w, wproj_hi, wproj_lo, n3);
    }

    // 1) QKV projection (mma.sync bf16x3): [S,1280] x [3840,1280]^T + b
    {
        cudaFuncSetAttribute(gemm_bf16x3, cudaFuncAttributeMaxDynamicSharedMemorySize, GEMM_SMEM);
        dim3 grid(QKV_N / BN, S_LEN / BM);
        gemm_bf16x3<<<grid, 256, GEMM_SMEM>>>(hid_hi, hid_lo, wqkv_hi, wqkv_lo,
                                              qkv_b, qkv_buf, QKV_N);
    }

    // 2) windowed attention with fused RoPE (fp32), emits bf16 hi/lo
    {
        const int smem = (3 * WS_WIN * Q_LD + WS_WIN * P_LD) * (int)sizeof(float);
        cudaFuncSetAttribute(attn_kernel, cudaFuncAttributeMaxDynamicSharedMemorySize, smem);
        attn_kernel<<<NW_WIN * H_NUM, 256, smem>>>(qkv_buf, masks, cosv, sinv, attn_hi, attn_lo);
    }

    // 3) output projection (mma.sync bf16x3): [S,1280] x [1280,1280]^T + b
    {
        dim3 grid(D_HID / BN, S_LEN / BM);
        gemm_bf16x3<<<grid, 256, GEMM_SMEM>>>(attn_hi, attn_lo, wproj_hi, wproj_lo,
                                              proj_b, out, D_HID);
    }
}

// round 4
// speedup vs baseline: 1.6893x; 1.0203x over previous
#include <cuda_runtime.h>
#include <cuda_bf16.h>
#include <cstdint>
#include <cstddef>

// ---------------------------------------------------------------------------
// Problem constants
// ---------------------------------------------------------------------------
#define S_LEN 16384
#define D_HID 1280
#define H_NUM 16
#define HD_DIM 80
#define WS_WIN 64
#define NW_WIN (S_LEN / WS_WIN)   // 256
#define QKV_N (3 * D_HID)         // 3840
#define KDIM 1280

// GEMM tiling: CTA 128x256, BK=32, 8 warps (2Mx4N), warp tile 64x64
#define BM 128
#define BN 256
#define BK 32
#define STAGES 3
#define KT_ITERS (KDIM / BK)      // 40
// per stage: Ah 8K, Al 8K, Bh 16K, Bl 16K = 48K
#define STAGE_BYTES 49152
#define GEMM_SMEM (STAGES * STAGE_BYTES)   // 147456

// ---------------------------------------------------------------------------
// Scratch (device globals: allocation-free contract)
// ---------------------------------------------------------------------------
__device__ float g_qkv[(size_t)S_LEN * QKV_N];
__device__ __nv_bfloat16 g_hid_hi[(size_t)S_LEN * D_HID];
__device__ __nv_bfloat16 g_hid_lo[(size_t)S_LEN * D_HID];
__device__ __nv_bfloat16 g_wqkv_hi[(size_t)QKV_N * D_HID];
__device__ __nv_bfloat16 g_wqkv_lo[(size_t)QKV_N * D_HID];
__device__ __nv_bfloat16 g_wproj_hi[(size_t)D_HID * D_HID];
__device__ __nv_bfloat16 g_wproj_lo[(size_t)D_HID * D_HID];
__device__ __nv_bfloat16 g_attn_hi[(size_t)S_LEN * D_HID];
__device__ __nv_bfloat16 g_attn_lo[(size_t)S_LEN * D_HID];

// ---------------------------------------------------------------------------
// PTX helpers (baseline sm_80+ only -- harness targets plain sm_100)
// ---------------------------------------------------------------------------
__device__ __forceinline__ uint32_t smem_u32(const void* p) {
    uint32_t a;
    asm("{ .reg .u64 t; cvta.to.shared.u64 t, %1; cvt.u32.u64 %0, t; }"
        : "=r"(a) : "l"(p));
    return a;
}

#define CP_ASYNC16(smem_addr, gptr) \
    asm volatile("cp.async.cg.shared.global [%0], [%1], 16;\n" \
                 :: "r"(smem_addr), "l"(gptr))
#define CP_ASYNC_COMMIT() asm volatile("cp.async.commit_group;\n" ::: "memory")
#define CP_ASYNC_WAIT1()  asm volatile("cp.async.wait_group 1;\n" ::: "memory")

#define LDSM_X4(r0, r1, r2, r3, addr) \
    asm volatile("ldmatrix.sync.aligned.m8n8.x4.shared.b16 {%0,%1,%2,%3}, [%4];" \
                 : "=r"(r0), "=r"(r1), "=r"(r2), "=r"(r3) : "r"(addr))

#define MMA16816(d, a0, a1, a2, a3, b0, b1) \
    asm volatile("mma.sync.aligned.m16n8k16.row.col.f32.bf16.bf16.f32 " \
                 "{%0,%1,%2,%3}, {%4,%5,%6,%7}, {%8,%9}, {%0,%1,%2,%3};" \
                 : "+f"((d)[0]), "+f"((d)[1]), "+f"((d)[2]), "+f"((d)[3]) \
                 : "r"(a0), "r"(a1), "r"(a2), "r"(a3), "r"(b0), "r"(b1))

// ---------------------------------------------------------------------------
// bf16x3 mma.sync GEMM: C[M, Ntot] = A[M,1280] * B[Ntot,1280]^T + bias
// ---------------------------------------------------------------------------
__global__ void __launch_bounds__(256, 1) gemm_bf16x3(
    const __nv_bfloat16* __restrict__ Ah, const __nv_bfloat16* __restrict__ Al,
    const __nv_bfloat16* __restrict__ Bh, const __nv_bfloat16* __restrict__ Bl,
    const float* __restrict__ bias, float* __restrict__ C, int Ntot)
{
    extern __shared__ char smem[];
    const uint32_t sb = smem_u32(smem);
    const int tid = threadIdx.x;
    const int wid = tid >> 5, lane = tid & 31;
    const int warp_m = wid & 1;        // 0..1 (64-row slabs)
    const int warp_n = wid >> 1;       // 0..3 (64-col slabs)
    const int m0 = blockIdx.y * BM;
    const int n0 = blockIdx.x * BN;

    // ---- per-thread cp.async mapping: 12 chunks of 16B per stage ----
    // stage layout: Ah[128][32]@0, Al@8192, Bh[256][32]@16384, Bl@32768
    const __nv_bfloat16* gptr[12];
    uint32_t soff[12];
    #pragma unroll
    for (int t = 0; t < 12; t++) {
        const int idx = tid + t * 256;         // 0..3071
        const __nv_bfloat16* base;
        int row, c;
        uint32_t mbase;
        int r0;
        if (idx < 1024) {                       // A half (Ah, Al)
            const int mat = idx >> 9;           // 0:Ah 1:Al
            const int li = idx & 511;
            row = li >> 2; c = li & 3;
            base = mat ? Al : Ah;
            mbase = (uint32_t)(mat * 8192);
            r0 = m0 + row;
        } else {                                // B half (Bh, Bl)
            const int j = idx - 1024;
            const int mat = j >> 10;            // 0:Bh 1:Bl
            const int li = j & 1023;
            row = li >> 2; c = li & 3;
            base = mat ? Bl : Bh;
            mbase = (uint32_t)(16384 + mat * 16384);
            r0 = n0 + row;
        }
        gptr[t] = base + (size_t)r0 * KDIM + c * 8;
        soff[t] = mbase + (uint32_t)(row * 64 + ((c ^ ((row >> 1) & 3)) << 4));
    }

    // ---- prefetch first STAGES-1 stages ----
    #pragma unroll
    for (int s = 0; s < STAGES - 1; s++) {
        const int kb = s * BK;
        #pragma unroll
        for (int t = 0; t < 12; t++)
            CP_ASYNC16(sb + s * STAGE_BYTES + soff[t], gptr[t] + kb);
        CP_ASYNC_COMMIT();
    }

    // ---- ldmatrix address precompute ----
    const int row_in = lane & 15;
    const int csel = lane >> 4;                 // 0/1: which 16B chunk pair
    uint32_t aRowOff[4], aXr[4];
    #pragma unroll
    for (int fm = 0; fm < 4; fm++) {
        const int r = warp_m * 64 + fm * 16 + row_in;
        aRowOff[fm] = (uint32_t)(r * 64);
        aXr[fm] = (uint32_t)((r >> 1) & 3);
    }
    uint32_t bRowOff[4], bXr[4];
    #pragma unroll
    for (int bt = 0; bt < 4; bt++) {
        const int r = warp_n * 64 + bt * 16 + row_in;
        bRowOff[bt] = (uint32_t)(16384 + r * 64);   // Bh base; +16384 for Bl
        bXr[bt] = (uint32_t)((r >> 1) & 3);
    }

    float acc[4][8][4];
    #pragma unroll
    for (int i = 0; i < 4; i++)
        #pragma unroll
        for (int j = 0; j < 8; j++)
            #pragma unroll
            for (int k = 0; k < 4; k++) acc[i][j][k] = 0.f;

    // ---- main loop ----
    for (int kt = 0; kt < KT_ITERS; kt++) {
        CP_ASYNC_WAIT1();
        __syncthreads();

        if (kt + STAGES - 1 < KT_ITERS) {
            const int s = (kt + STAGES - 1) % STAGES;
            const int kb = (kt + STAGES - 1) * BK;
            #pragma unroll
            for (int t = 0; t < 12; t++)
                CP_ASYNC16(sb + s * STAGE_BYTES + soff[t], gptr[t] + kb);
        }
        CP_ASYNC_COMMIT();

        const uint32_t stg = sb + (kt % STAGES) * STAGE_BYTES;

        #pragma unroll
        for (int kk = 0; kk < 2; kk++) {
            const uint32_t chunk = (uint32_t)(kk * 2 + csel);

            // B fragments: 8 n8 frags x {hi,lo}
            uint32_t bh[8][2], bl[8][2];
            #pragma unroll
            for (int bt = 0; bt < 4; bt++) {
                const uint32_t xoff = ((chunk ^ bXr[bt]) << 4);
                uint32_t r0, r1, r2, r3;
                LDSM_X4(r0, r1, r2, r3, stg + bRowOff[bt] + xoff);
                bh[bt * 2 + 0][0] = r0; bh[bt * 2 + 1][0] = r1;
                bh[bt * 2 + 0][1] = r2; bh[bt * 2 + 1][1] = r3;
                LDSM_X4(r0, r1, r2, r3, stg + 16384 + bRowOff[bt] + xoff);
                bl[bt * 2 + 0][0] = r0; bl[bt * 2 + 1][0] = r1;
                bl[bt * 2 + 0][1] = r2; bl[bt * 2 + 1][1] = r3;
            }

            #pragma unroll
            for (int fm = 0; fm < 4; fm++) {
                const uint32_t xoff = ((chunk ^ aXr[fm]) << 4);
                uint32_t ah0, ah1, ah2, ah3, al0, al1, al2, al3;
                LDSM_X4(ah0, ah1, ah2, ah3, stg + aRowOff[fm] + xoff);
                LDSM_X4(al0, al1, al2, al3, stg + 8192 + aRowOff[fm] + xoff);
                #pragma unroll
                for (int fn = 0; fn < 8; fn++) {
                    MMA16816(acc[fm][fn], ah0, ah1, ah2, ah3, bh[fn][0], bh[fn][1]);
                    MMA16816(acc[fm][fn], ah0, ah1, ah2, ah3, bl[fn][0], bl[fn][1]);
                    MMA16816(acc[fm][fn], al0, al1, al2, al3, bh[fn][0], bh[fn][1]);
                }
            }
        }
    }

    // ---- epilogue: bias + coalesced STG.64 ----
    const int tr = lane >> 2;
    const int tc = (lane & 3) * 2;
    const int r_base = m0 + warp_m * 64;
    const int c_base = n0 + warp_n * 64;
    #pragma unroll
    for (int fn = 0; fn < 8; fn++) {
        const int col = c_base + fn * 8 + tc;
        const float2 bb = *(const float2*)&bias[col];
        #pragma unroll
        for (int fm = 0; fm < 4; fm++) {
            const int row0 = r_base + fm * 16 + tr;
            float2 v0, v1;
            v0.x = acc[fm][fn][0] + bb.x; v0.y = acc[fm][fn][1] + bb.y;
            v1.x = acc[fm][fn][2] + bb.x; v1.y = acc[fm][fn][3] + bb.y;
            *(float2*)&C[(size_t)row0 * Ntot + col] = v0;
            *(float2*)&C[(size_t)(row0 + 8) * Ntot + col] = v1;
        }
    }
}

// ---------------------------------------------------------------------------
// fp32 -> bf16 (hi, lo) split
// ---------------------------------------------------------------------------
__global__ void split_bf16(const float* __restrict__ src,
                           __nv_bfloat16* __restrict__ hi,
                           __nv_bfloat16* __restrict__ lo, int n)
{
    int i = blockIdx.x * blockDim.x + threadIdx.x;
    if (i < n) {
        float x = src[i];
        __nv_bfloat16 h = __float2bfloat16(x);
        hi[i] = h;
        lo[i] = __float2bfloat16(x - __bfloat162float(h));
    }
}

// ---------------------------------------------------------------------------
// Windowed attention (fp32), one block per (window, head).
// ---------------------------------------------------------------------------
#define Q_LD 81
#define P_LD 65

__global__ void __launch_bounds__(256) attn_kernel(
    const float* __restrict__ qkv,
    const float* __restrict__ mask,
    const float* __restrict__ cosv,
    const float* __restrict__ sinv,
    __nv_bfloat16* __restrict__ out_hi,
    __nv_bfloat16* __restrict__ out_lo)
{
    extern __shared__ float sm[];
    float* qs = sm;
    float* ks = qs + 64 * Q_LD;
    float* vs = ks + 64 * Q_LD;
    float* ps = vs + 64 * Q_LD;

    const int w = blockIdx.x >> 4;
    const int h = blockIdx.x & 15;
    const int tid = threadIdx.x;

    for (int idx = tid; idx < WS_WIN * HD_DIM; idx += 256) {
        const int p = idx / HD_DIM, d = idx % HD_DIM;
        const int s = w * WS_WIN + p;
        const size_t base = (size_t)s * QKV_N + h * HD_DIM;
        const float c  = cosv[s * HD_DIM + d];
        const float sn = sinv[s * HD_DIM + d];
        const int pd   = (d < 40) ? (d + 40) : (d - 40);
        const float sg = (d < 40) ? -1.f : 1.f;

        float qv = qkv[base + d];
        float qp = qkv[base + pd];
        qs[p * Q_LD + d] = qv * c + sg * qp * sn;

        float kv = qkv[base + D_HID + d];
        float kp = qkv[base + D_HID + pd];
        ks[p * Q_LD + d] = kv * c + sg * kp * sn;

        vs[p * Q_LD + d] = qkv[base + 2 * D_HID + d];
    }
    __syncthreads();

    const float scale = 0.1118033988749895f;
    const int warp = tid >> 5, lane = tid & 31;
    const float* mrow_base = mask + (size_t)w * (WS_WIN * WS_WIN);

    #pragma unroll
    for (int i = 0; i < 8; i++) {
        const int r = warp * 8 + i;
        float v0 = 0.f, v1 = 0.f;
        const float* qrow = &qs[r * Q_LD];
        const float* k0 = &ks[lane * Q_LD];
        const float* k1 = &ks[(lane + 32) * Q_LD];
        #pragma unroll 8
        for (int d = 0; d < HD_DIM; d++) {
            const float qd = qrow[d];
            v0 = fmaf(qd, k0[d], v0);
            v1 = fmaf(qd, k1[d], v1);
        }
        v0 = v0 * scale + mrow_base[r * WS_WIN + lane];
        v1 = v1 * scale + mrow_base[r * WS_WIN + lane + 32];

        float mx = fmaxf(v0, v1);
        #pragma unroll
        for (int o = 16; o > 0; o >>= 1)
            mx = fmaxf(mx, __shfl_xor_sync(0xffffffffu, mx, o));
        const float e0 = __expf(v0 - mx);
        const float e1 = __expf(v1 - mx);
        float ssum = e0 + e1;
        #pragma unroll
        for (int o = 16; o > 0; o >>= 1)
            ssum += __shfl_xor_sync(0xffffffffu, ssum, o);
        const float inv = 1.f / ssum;
        ps[r * P_LD + lane]      = e0 * inv;
        ps[r * P_LD + lane + 32] = e1 * inv;
    }
    __syncthreads();

    for (int idx = tid; idx < WS_WIN * HD_DIM; idx += 256) {
        const int r = idx / HD_DIM, d = idx % HD_DIM;
        const float* prow = &ps[r * P_LD];
        float acc = 0.f;
        #pragma unroll 8
        for (int c = 0; c < WS_WIN; c++)
            acc = fmaf(prow[c], vs[c * Q_LD + d], acc);
        const size_t o = (size_t)(w * WS_WIN + r) * D_HID + h * HD_DIM + d;
        __nv_bfloat16 hh = __float2bfloat16(acc);
        out_hi[o] = hh;
        out_lo[o] = __float2bfloat16(acc - __bfloat162float(hh));
    }
}

// ---------------------------------------------------------------------------
// launch
// ---------------------------------------------------------------------------
extern "C" void kernel_launch(void* const* d_in, const int* in_sizes, int n_in,
                              void* d_out, int out_size)
{
    (void)in_sizes; (void)n_in; (void)out_size;
    const float* hidden = (const float*)d_in[0];
    const float* masks  = (const float*)d_in[1];
    const float* cosv   = (const float*)d_in[2];
    const float* sinv   = (const float*)d_in[3];
    const float* qkv_w  = (const float*)d_in[4];
    const float* qkv_b  = (const float*)d_in[5];
    const float* proj_w = (const float*)d_in[6];
    const float* proj_b = (const float*)d_in[7];
    float* out = (float*)d_out;

    float* qkv_buf;
    __nv_bfloat16 *hid_hi, *hid_lo, *wqkv_hi, *wqkv_lo, *wproj_hi, *wproj_lo, *attn_hi, *attn_lo;
    cudaGetSymbolAddress((void**)&qkv_buf, g_qkv);
    cudaGetSymbolAddress((void**)&hid_hi, g_hid_hi);
    cudaGetSymbolAddress((void**)&hid_lo, g_hid_lo);
    cudaGetSymbolAddress((void**)&wqkv_hi, g_wqkv_hi);
    cudaGetSymbolAddress((void**)&wqkv_lo, g_wqkv_lo);
    cudaGetSymbolAddress((void**)&wproj_hi, g_wproj_hi);
    cudaGetSymbolAddress((void**)&wproj_lo, g_wproj_lo);
    cudaGetSymbolAddress((void**)&attn_hi, g_attn_hi);
    cudaGetSymbolAddress((void**)&attn_lo, g_attn_lo);

    // 0) fp32 -> bf16 hi/lo splits
    {
        int n1 = S_LEN * D_HID;
        split_bf16<<<(n1 + 255) / 256, 256>>>(hidden, hid_hi, hid_lo, n1);
        int n2 = QKV_N * D_HID;
        split_bf16<<<(n2 + 255) / 256, 256>>>(qkv_w, wqkv_hi, wqkv_lo, n2);
        int n3 = D_HID * D_HID;
        split_bf16<<<(n3 + 255) / 256, 256>>>(proj_w, wproj_hi, wproj_lo, n3);
    }

    // 1) QKV projection (mma.sync bf16x3): [S,1280] x [3840,1280]^T + b
    {
        cudaFuncSetAttribute(gemm_bf16x3, cudaFuncAttributeMaxDynamicSharedMemorySize, GEMM_SMEM);
        dim3 grid(QKV_N / BN, S_LEN / BM);
        gemm_bf16x3<<<grid, 256, GEMM_SMEM>>>(hid_hi, hid_lo, wqkv_hi, wqkv_lo,
                                              qkv_b, qkv_buf, QKV_N);
    }

    // 2) windowed attention with fused RoPE (fp32), emits bf16 hi/lo
    {
        const int smem = (3 * WS_WIN * Q_LD + WS_WIN * P_LD) * (int)sizeof(float);
        cudaFuncSetAttribute(attn_kernel, cudaFuncAttributeMaxDynamicSharedMemorySize, smem);
        attn_kernel<<<NW_WIN * H_NUM, 256, smem>>>(qkv_buf, masks, cosv, sinv, attn_hi, attn_lo);
    }

    // 3) output projection (mma.sync bf16x3): [S,1280] x [1280,1280]^T + b
    {
        dim3 grid(D_HID / BN, S_LEN / BM);
        gemm_bf16x3<<<grid, 256, GEMM_SMEM>>>(attn_hi, attn_lo, wproj_hi, wproj_lo,
                                              proj_b, out, D_HID);
    }
}

// round 5
// speedup vs baseline: 1.7506x; 1.0363x over previous
#include <cuda_runtime.h>
#include <cuda_bf16.h>
#include <cstdint>
#include <cstddef>

// ---------------------------------------------------------------------------
// Problem constants
// ---------------------------------------------------------------------------
#define S_LEN 16384
#define D_HID 1280
#define H_NUM 16
#define HD_DIM 80
#define WS_WIN 64
#define NW_WIN (S_LEN / WS_WIN)   // 256
#define QKV_N (3 * D_HID)         // 3840
#define KDIM 1280

// GEMM tiling: CTA 128x256, BK=32, 8 warps (2Mx4N), warp tile 64x64
#define BM 128
#define BN 256
#define BK 32
#define STAGES 3
#define KT_ITERS (KDIM / BK)      // 40
#define STAGE_BYTES 49152         // Ah 8K | Al 8K | Bh 16K | Bl 16K
#define GEMM_SMEM (STAGES * STAGE_BYTES)   // 147456

// ---------------------------------------------------------------------------
// Scratch (device globals: allocation-free contract)
// ---------------------------------------------------------------------------
__device__ float g_qkv[(size_t)S_LEN * QKV_N];
__device__ __nv_bfloat16 g_hid_hi[(size_t)S_LEN * D_HID];
__device__ __nv_bfloat16 g_hid_lo[(size_t)S_LEN * D_HID];
__device__ __nv_bfloat16 g_wqkv_hi[(size_t)QKV_N * D_HID];
__device__ __nv_bfloat16 g_wqkv_lo[(size_t)QKV_N * D_HID];
__device__ __nv_bfloat16 g_wproj_hi[(size_t)D_HID * D_HID];
__device__ __nv_bfloat16 g_wproj_lo[(size_t)D_HID * D_HID];
__device__ __nv_bfloat16 g_attn_hi[(size_t)S_LEN * D_HID];
__device__ __nv_bfloat16 g_attn_lo[(size_t)S_LEN * D_HID];

// ---------------------------------------------------------------------------
// PTX helpers (baseline sm_80+ only -- harness targets plain sm_100)
// ---------------------------------------------------------------------------
__device__ __forceinline__ uint32_t smem_u32(const void* p) {
    uint32_t a;
    asm("{ .reg .u64 t; cvta.to.shared.u64 t, %1; cvt.u32.u64 %0, t; }"
        : "=r"(a) : "l"(p));
    return a;
}

#define CP_ASYNC16(smem_addr, gptr) \
    asm volatile("cp.async.cg.shared.global [%0], [%1], 16;\n" \
                 :: "r"(smem_addr), "l"(gptr))
#define CP_ASYNC_COMMIT() asm volatile("cp.async.commit_group;\n" ::: "memory")
#define CP_ASYNC_WAIT1()  asm volatile("cp.async.wait_group 1;\n" ::: "memory")

#define LDSM_X4(r0, r1, r2, r3, addr) \
    asm volatile("ldmatrix.sync.aligned.m8n8.x4.shared.b16 {%0,%1,%2,%3}, [%4];" \
                 : "=r"(r0), "=r"(r1), "=r"(r2), "=r"(r3) : "r"(addr))

#define MMA16816(d, a0, a1, a2, a3, b0, b1) \
    asm volatile("mma.sync.aligned.m16n8k16.row.col.f32.bf16.bf16.f32 " \
                 "{%0,%1,%2,%3}, {%4,%5,%6,%7}, {%8,%9}, {%0,%1,%2,%3};" \
                 : "+f"((d)[0]), "+f"((d)[1]), "+f"((d)[2]), "+f"((d)[3]) \
                 : "r"(a0), "r"(a1), "r"(a2), "r"(a3), "r"(b0), "r"(b1))

// ---------------------------------------------------------------------------
// bf16x3 mma.sync GEMM: C[M, Ntot] = A[M,1280] * B[Ntot,1280]^T + bias
// ---------------------------------------------------------------------------
__global__ void __launch_bounds__(256, 1) gemm_bf16x3(
    const __nv_bfloat16* __restrict__ Ah, const __nv_bfloat16* __restrict__ Al,
    const __nv_bfloat16* __restrict__ Bh, const __nv_bfloat16* __restrict__ Bl,
    const float* __restrict__ bias, float* __restrict__ C, int Ntot)
{
    extern __shared__ char smem[];
    const uint32_t sb = smem_u32(smem);
    const int tid = threadIdx.x;
    const int wid = tid >> 5, lane = tid & 31;
    const int warp_m = wid & 1;        // 0..1 (64-row slabs)
    const int warp_n = wid >> 1;       // 0..3 (64-col slabs)
    const int m0 = blockIdx.y * BM;
    const int n0 = blockIdx.x * BN;

    // ---- per-thread cp.async mapping: 12 chunks of 16B per stage ----
    const __nv_bfloat16* gptr[12];
    uint32_t soff[12];
    #pragma unroll
    for (int t = 0; t < 12; t++) {
        const int idx = tid + t * 256;         // 0..3071
        const __nv_bfloat16* base;
        int row, c;
        uint32_t mbase;
        int r0;
        if (idx < 1024) {                       // A half (Ah, Al)
            const int mat = idx >> 9;
            const int li = idx & 511;
            row = li >> 2; c = li & 3;
            base = mat ? Al : Ah;
            mbase = (uint32_t)(mat * 8192);
            r0 = m0 + row;
        } else {                                // B half (Bh, Bl)
            const int j = idx - 1024;
            const int mat = j >> 10;
            const int li = j & 1023;
            row = li >> 2; c = li & 3;
            base = mat ? Bl : Bh;
            mbase = (uint32_t)(16384 + mat * 16384);
            r0 = n0 + row;
        }
        gptr[t] = base + (size_t)r0 * KDIM + c * 8;
        soff[t] = mbase + (uint32_t)(row * 64 + ((c ^ ((row >> 1) & 3)) << 4));
    }

    // ---- prefetch first STAGES-1 stages ----
    #pragma unroll
    for (int s = 0; s < STAGES - 1; s++) {
        const int kb = s * BK;
        #pragma unroll
        for (int t = 0; t < 12; t++)
            CP_ASYNC16(sb + s * STAGE_BYTES + soff[t], gptr[t] + kb);
        CP_ASYNC_COMMIT();
    }

    // ---- ldmatrix base offsets (chunk=csel), fully swizzled ----
    const int row_in = lane & 15;
    const int csel = lane >> 4;                 // chunk bit0
    uint32_t aOff[4], bOff[4];
    #pragma unroll
    for (int fm = 0; fm < 4; fm++) {
        const int r = warp_m * 64 + fm * 16 + row_in;
        aOff[fm] = (uint32_t)(r * 64 + (((uint32_t)csel ^ ((r >> 1) & 3)) << 4));
    }
    #pragma unroll
    for (int bt = 0; bt < 4; bt++) {
        const int r = warp_n * 64 + bt * 16 + row_in;
        bOff[bt] = (uint32_t)(16384 + r * 64 + (((uint32_t)csel ^ ((r >> 1) & 3)) << 4));
    }

    float acc[4][8][4];
    #pragma unroll
    for (int i = 0; i < 4; i++)
        #pragma unroll
        for (int j = 0; j < 8; j++)
            #pragma unroll
            for (int k = 0; k < 4; k++) acc[i][j][k] = 0.f;

    // ---- main loop ----
    for (int kt = 0; kt < KT_ITERS; kt++) {
        CP_ASYNC_WAIT1();
        __syncthreads();

        if (kt + STAGES - 1 < KT_ITERS) {
            const int s = (kt + STAGES - 1) % STAGES;
            const int kb = (kt + STAGES - 1) * BK;
            #pragma unroll
            for (int t = 0; t < 12; t++)
                CP_ASYNC16(sb + s * STAGE_BYTES + soff[t], gptr[t] + kb);
        }
        CP_ASYNC_COMMIT();

        const uint32_t stg = sb + (kt % STAGES) * STAGE_BYTES;

        #pragma unroll
        for (int kk = 0; kk < 2; kk++) {
            const uint32_t kx = (uint32_t)(kk * 0x20);   // chunk bit1 -> addr bit5

            uint32_t bh[8][2], bl[8][2];
            #pragma unroll
            for (int bt = 0; bt < 4; bt++) {
                const uint32_t ad = stg + (bOff[bt] ^ kx);
                uint32_t r0, r1, r2, r3;
                LDSM_X4(r0, r1, r2, r3, ad);
                bh[bt * 2 + 0][0] = r0; bh[bt * 2 + 1][0] = r1;
                bh[bt * 2 + 0][1] = r2; bh[bt * 2 + 1][1] = r3;
                LDSM_X4(r0, r1, r2, r3, ad + 16384);
                bl[bt * 2 + 0][0] = r0; bl[bt * 2 + 1][0] = r1;
                bl[bt * 2 + 0][1] = r2; bl[bt * 2 + 1][1] = r3;
            }
            uint32_t ah[4][4], al[4][4];
            #pragma unroll
            for (int fm = 0; fm < 4; fm++) {
                const uint32_t ad = stg + (aOff[fm] ^ kx);
                LDSM_X4(ah[fm][0], ah[fm][1], ah[fm][2], ah[fm][3], ad);
                LDSM_X4(al[fm][0], al[fm][1], al[fm][2], al[fm][3], ad + 8192);
            }

            // term-major ordering: consecutive MMAs hit different accumulators
            #pragma unroll
            for (int fm = 0; fm < 4; fm++)
                #pragma unroll
                for (int fn = 0; fn < 8; fn++)
                    MMA16816(acc[fm][fn], ah[fm][0], ah[fm][1], ah[fm][2], ah[fm][3],
                             bh[fn][0], bh[fn][1]);
            #pragma unroll
            for (int fm = 0; fm < 4; fm++)
                #pragma unroll
                for (int fn = 0; fn < 8; fn++)
                    MMA16816(acc[fm][fn], ah[fm][0], ah[fm][1], ah[fm][2], ah[fm][3],
                             bl[fn][0], bl[fn][1]);
            #pragma unroll
            for (int fm = 0; fm < 4; fm++)
                #pragma unroll
                for (int fn = 0; fn < 8; fn++)
                    MMA16816(acc[fm][fn], al[fm][0], al[fm][1], al[fm][2], al[fm][3],
                             bh[fn][0], bh[fn][1]);
        }
    }

    // ---- epilogue: bias + coalesced STG.64 ----
    const int tr = lane >> 2;
    const int tc = (lane & 3) * 2;
    const int r_base = m0 + warp_m * 64;
    const int c_base = n0 + warp_n * 64;
    #pragma unroll
    for (int fn = 0; fn < 8; fn++) {
        const int col = c_base + fn * 8 + tc;
        const float2 bb = *(const float2*)&bias[col];
        #pragma unroll
        for (int fm = 0; fm < 4; fm++) {
            const int row0 = r_base + fm * 16 + tr;
            float2 v0, v1;
            v0.x = acc[fm][fn][0] + bb.x; v0.y = acc[fm][fn][1] + bb.y;
            v1.x = acc[fm][fn][2] + bb.x; v1.y = acc[fm][fn][3] + bb.y;
            *(float2*)&C[(size_t)row0 * Ntot + col] = v0;
            *(float2*)&C[(size_t)(row0 + 8) * Ntot + col] = v1;
        }
    }
}

// ---------------------------------------------------------------------------
// fp32 -> bf16 (hi, lo) split
// ---------------------------------------------------------------------------
__global__ void split_bf16(const float* __restrict__ src,
                           __nv_bfloat16* __restrict__ hi,
                           __nv_bfloat16* __restrict__ lo, int n)
{
    int i = blockIdx.x * blockDim.x + threadIdx.x;
    if (i < n) {
        float x = src[i];
        __nv_bfloat16 h = __float2bfloat16(x);
        hi[i] = h;
        lo[i] = __float2bfloat16(x - __bfloat162float(h));
    }
}

// ---------------------------------------------------------------------------
// Windowed attention (fp32), one block per (window, head).
// Phase 1: float4 raw copy q/k/v into smem. Phase 2: in-smem RoPE.
// ---------------------------------------------------------------------------
#define Q_LD 81
#define P_LD 65

__global__ void __launch_bounds__(256) attn_kernel(
    const float* __restrict__ qkv,
    const float* __restrict__ mask,
    const float* __restrict__ cosv,
    const float* __restrict__ sinv,
    __nv_bfloat16* __restrict__ out_hi,
    __nv_bfloat16* __restrict__ out_lo)
{
    extern __shared__ float sm[];
    float* qs = sm;
    float* ks = qs + 64 * Q_LD;
    float* vs = ks + 64 * Q_LD;
    float* ps = vs + 64 * Q_LD;

    const int w = blockIdx.x >> 4;
    const int h = blockIdx.x & 15;
    const int tid = threadIdx.x;

    // phase 1: streaming float4 copy (q, k, v raw)
    for (int u = tid; u < 64 * 20 * 3; u += 256) {
        const int mat = u / (64 * 20);          // 0:q 1:k 2:v
        const int li = u % (64 * 20);
        const int p = li / 20, c4 = li % 20;
        const int s = w * WS_WIN + p;
        const float4 v = *(const float4*)&qkv[(size_t)s * QKV_N + mat * D_HID + h * HD_DIM + c4 * 4];
        float* dst = (mat == 0 ? qs : mat == 1 ? ks : vs) + p * Q_LD + c4 * 4;
        dst[0] = v.x; dst[1] = v.y; dst[2] = v.z; dst[3] = v.w;
    }
    __syncthreads();

    // phase 2: in-smem RoPE on q, k (pairs d, d+40)
    for (int u = tid; u < 64 * 40; u += 256) {
        const int p = u / 40, d = u % 40;
        const int s = w * WS_WIN + p;
        const float c0 = cosv[s * HD_DIM + d];
        const float c1 = cosv[s * HD_DIM + d + 40];
        const float s0 = sinv[s * HD_DIM + d];
        const float s1 = sinv[s * HD_DIM + d + 40];

        float* qp = &qs[p * Q_LD];
        const float q0 = qp[d], q1 = qp[d + 40];
        qp[d]      = q0 * c0 - q1 * s0;
        qp[d + 40] = q1 * c1 + q0 * s1;

        float* kp = &ks[p * Q_LD];
        const float k0 = kp[d], k1 = kp[d + 40];
        kp[d]      = k0 * c0 - k1 * s0;
        kp[d + 40] = k1 * c1 + k0 * s1;
    }
    __syncthreads();

    const float scale = 0.1118033988749895f;
    const int warp = tid >> 5, lane = tid & 31;
    const float* mrow_base = mask + (size_t)w * (WS_WIN * WS_WIN);

    #pragma unroll
    for (int i = 0; i < 8; i++) {
        const int r = warp * 8 + i;
        float v0 = 0.f, v1 = 0.f;
        const float* qrow = &qs[r * Q_LD];
        const float* k0 = &ks[lane * Q_LD];
        const float* k1 = &ks[(lane + 32) * Q_LD];
        #pragma unroll 8
        for (int d = 0; d < HD_DIM; d++) {
            const float qd = qrow[d];
            v0 = fmaf(qd, k0[d], v0);
            v1 = fmaf(qd, k1[d], v1);
        }
        v0 = v0 * scale + mrow_base[r * WS_WIN + lane];
        v1 = v1 * scale + mrow_base[r * WS_WIN + lane + 32];

        float mx = fmaxf(v0, v1);
        #pragma unroll
        for (int o = 16; o > 0; o >>= 1)
            mx = fmaxf(mx, __shfl_xor_sync(0xffffffffu, mx, o));
        const float e0 = __expf(v0 - mx);
        const float e1 = __expf(v1 - mx);
        float ssum = e0 + e1;
        #pragma unroll
        for (int o = 16; o > 0; o >>= 1)
            ssum += __shfl_xor_sync(0xffffffffu, ssum, o);
        const float inv = 1.f / ssum;
        ps[r * P_LD + lane]      = e0 * inv;
        ps[r * P_LD + lane + 32] = e1 * inv;
    }
    __syncthreads();

    for (int idx = tid; idx < WS_WIN * HD_DIM; idx += 256) {
        const int r = idx / HD_DIM, d = idx % HD_DIM;
        const float* prow = &ps[r * P_LD];
        float acc = 0.f;
        #pragma unroll 8
        for (int c = 0; c < WS_WIN; c++)
            acc = fmaf(prow[c], vs[c * Q_LD + d], acc);
        const size_t o = (size_t)(w * WS_WIN + r) * D_HID + h * HD_DIM + d;
        __nv_bfloat16 hh = __float2bfloat16(acc);
        out_hi[o] = hh;
        out_lo[o] = __float2bfloat16(acc - __bfloat162float(hh));
    }
}

// ---------------------------------------------------------------------------
// launch
// ---------------------------------------------------------------------------
extern "C" void kernel_launch(void* const* d_in, const int* in_sizes, int n_in,
                              void* d_out, int out_size)
{
    (void)in_sizes; (void)n_in; (void)out_size;
    const float* hidden = (const float*)d_in[0];
    const float* masks  = (const float*)d_in[1];
    const float* cosv   = (const float*)d_in[2];
    const float* sinv   = (const float*)d_in[3];
    const float* qkv_w  = (const float*)d_in[4];
    const float* qkv_b  = (const float*)d_in[5];
    const float* proj_w = (const float*)d_in[6];
    const float* proj_b = (const float*)d_in[7];
    float* out = (float*)d_out;

    float* qkv_buf;
    __nv_bfloat16 *hid_hi, *hid_lo, *wqkv_hi, *wqkv_lo, *wproj_hi, *wproj_lo, *attn_hi, *attn_lo;
    cudaGetSymbolAddress((void**)&qkv_buf, g_qkv);
    cudaGetSymbolAddress((void**)&hid_hi, g_hid_hi);
    cudaGetSymbolAddress((void**)&hid_lo, g_hid_lo);
    cudaGetSymbolAddress((void**)&wqkv_hi, g_wqkv_hi);
    cudaGetSymbolAddress((void**)&wqkv_lo, g_wqkv_lo);
    cudaGetSymbolAddress((void**)&wproj_hi, g_wproj_hi);
    cudaGetSymbolAddress((void**)&wproj_lo, g_wproj_lo);
    cudaGetSymbolAddress((void**)&attn_hi, g_attn_hi);
    cudaGetSymbolAddress((void**)&attn_lo, g_attn_lo);

    // 0) fp32 -> bf16 hi/lo splits
    {
        int n1 = S_LEN * D_HID;
        split_bf16<<<(n1 + 255) / 256, 256>>>(hidden, hid_hi, hid_lo, n1);
        int n2 = QKV_N * D_HID;
        split_bf16<<<(n2 + 255) / 256, 256>>>(qkv_w, wqkv_hi, wqkv_lo, n2);
        int n3 = D_HID * D_HID;
        split_bf16<<<(n3 + 255) / 256, 256>>>(proj_w, wproj_hi, wproj_lo, n3);
    }

    // 1) QKV projection (mma.sync bf16x3)
    {
        cudaFuncSetAttribute(gemm_bf16x3, cudaFuncAttributeMaxDynamicSharedMemorySize, GEMM_SMEM);
        dim3 grid(QKV_N / BN, S_LEN / BM);
        gemm_bf16x3<<<grid, 256, GEMM_SMEM>>>(hid_hi, hid_lo, wqkv_hi, wqkv_lo,
                                              qkv_b, qkv_buf, QKV_N);
    }

    // 2) windowed attention with fused RoPE (fp32), emits bf16 hi/lo
    {
        const int smem = (3 * WS_WIN * Q_LD + WS_WIN * P_LD) * (int)sizeof(float);
        cudaFuncSetAttribute(attn_kernel, cudaFuncAttributeMaxDynamicSharedMemorySize, smem);
        attn_kernel<<<NW_WIN * H_NUM, 256, smem>>>(qkv_buf, masks, cosv, sinv, attn_hi, attn_lo);
    }

    // 3) output projection (mma.sync bf16x3)
    {
        dim3 grid(D_HID / BN, S_LEN / BM);
        gemm_bf16x3<<<grid, 256, GEMM_SMEM>>>(attn_hi, attn_lo, wproj_hi, wproj_lo,
                                              proj_b, out, D_HID);
    }
}